// round 3
// baseline (speedup 1.0000x reference)
#include <cuda_runtime.h>
#include <cstdint>
#include <cstddef>

// Problem constants
#define BATCH 2
#define SEQ   2048
#define DM    768
#define NH    12
#define DHD   64
#define ATT_SCALE 0.125f   // 1/sqrt(64)
#define KB    64           // keys per fused k-block

// Scratch (allocation-free rule: __device__ globals)
__device__ float g_q[BATCH * SEQ * DM];
__device__ float g_k[BATCH * SEQ * DM];
__device__ float g_v[BATCH * SEQ * DM];
__device__ float g_attn[BATCH * SEQ * DM];

// ---------------------------------------------------------------------------
// tf32 helpers
// ---------------------------------------------------------------------------
__device__ __forceinline__ uint32_t f2tf32(float f) {
    uint32_t u;
    asm("cvt.rna.tf32.f32 %0, %1;" : "=r"(u) : "f"(f));
    return u;
}

__device__ __forceinline__ void mma8(float* c, const uint32_t* a, const uint32_t* b) {
    asm volatile(
        "mma.sync.aligned.m16n8k8.row.col.f32.tf32.tf32.f32 "
        "{%0,%1,%2,%3},{%4,%5,%6,%7},{%8,%9},{%0,%1,%2,%3};"
        : "+f"(c[0]), "+f"(c[1]), "+f"(c[2]), "+f"(c[3])
        : "r"(a[0]), "r"(a[1]), "r"(a[2]), "r"(a[3]), "r"(b[0]), "r"(b[1]));
}

// ===========================================================================
// Projection: Y[M,768] = X[M,768] @ W^T + bias.
// 128x128 CTA tile, BK=16, double-buffered smem + register prefetch.
// grid = (6, M/128), 256 threads (8 warps, 2x4; warp tile 64x32).
// ===========================================================================
__device__ __forceinline__ void proj_stage_load(
    const float* __restrict__ Ag, const float* __restrict__ Bg,
    int k0, int tid, float4 ar[2], float4 br[2])
{
    #pragma unroll
    for (int t = 0; t < 2; t++) {
        int i = tid + t * 256;
        ar[t] = *(const float4*)(Ag + (size_t)(i >> 2) * DM + k0 + (i & 3) * 4);
    }
    #pragma unroll
    for (int t = 0; t < 2; t++) {
        int i = tid + t * 256;
        br[t] = *(const float4*)(Bg + (size_t)(i >> 2) * DM + k0 + (i & 3) * 4);
    }
}

__device__ __forceinline__ void proj_stage_store(
    uint32_t As[16][136], uint32_t Bs[16][136],
    int tid, const float4 ar[2], const float4 br[2])
{
    #pragma unroll
    for (int t = 0; t < 2; t++) {
        int i = tid + t * 256;
        int r = i >> 2, c = (i & 3) * 4;
        As[c + 0][r] = f2tf32(ar[t].x);
        As[c + 1][r] = f2tf32(ar[t].y);
        As[c + 2][r] = f2tf32(ar[t].z);
        As[c + 3][r] = f2tf32(ar[t].w);
    }
    #pragma unroll
    for (int t = 0; t < 2; t++) {
        int i = tid + t * 256;
        int r = i >> 2, c = (i & 3) * 4;
        Bs[c + 0][r] = f2tf32(br[t].x);
        Bs[c + 1][r] = f2tf32(br[t].y);
        Bs[c + 2][r] = f2tf32(br[t].z);
        Bs[c + 3][r] = f2tf32(br[t].w);
    }
}

__device__ __forceinline__ void proj_tile_mma(
    const uint32_t As[16][136], const uint32_t Bs[16][136],
    int lane, int wm0, int wn0, float acc[4][4][4])
{
    const int g = lane >> 2, lq = lane & 3;
    #pragma unroll
    for (int ks = 0; ks < 16; ks += 8) {
        const int kb = ks + lq;
        uint32_t af[4][4], bf[4][2];
        #pragma unroll
        for (int mt = 0; mt < 4; mt++) {
            int m = wm0 + mt * 16 + g;
            af[mt][0] = As[kb][m];
            af[mt][1] = As[kb][m + 8];
            af[mt][2] = As[kb + 4][m];
            af[mt][3] = As[kb + 4][m + 8];
        }
        #pragma unroll
        for (int nt = 0; nt < 4; nt++) {
            int n = wn0 + nt * 8 + g;
            bf[nt][0] = Bs[kb][n];
            bf[nt][1] = Bs[kb + 4][n];
        }
        #pragma unroll
        for (int mt = 0; mt < 4; mt++)
            #pragma unroll
            for (int nt = 0; nt < 4; nt++)
                mma8(acc[mt][nt], af[mt], bf[nt]);
    }
}

__global__ __launch_bounds__(256, 2) void proj_kernel(
    const float* __restrict__ X, const float* __restrict__ W,
    const float* __restrict__ bias, float* __restrict__ Y)
{
    __shared__ uint32_t As[2][16][136];
    __shared__ uint32_t Bs[2][16][136];

    const int tid = threadIdx.x, lane = tid & 31, warp = tid >> 5;
    const int wm0 = (warp & 1) * 64, wn0 = (warp >> 1) * 32;
    const int row0 = blockIdx.y * 128, col0 = blockIdx.x * 128;
    const float* Ag = X + (size_t)row0 * DM;
    const float* Bg = W + (size_t)col0 * DM;

    float acc[4][4][4] = {};
    float4 ar[2], br[2];

    proj_stage_load(Ag, Bg, 0, tid, ar, br);
    proj_stage_store(As[0], Bs[0], tid, ar, br);
    __syncthreads();

    int buf = 0;
    for (int k0 = 16; k0 < DM; k0 += 16) {
        proj_stage_load(Ag, Bg, k0, tid, ar, br);     // prefetch next
        proj_tile_mma(As[buf], Bs[buf], lane, wm0, wn0, acc);
        proj_stage_store(As[buf ^ 1], Bs[buf ^ 1], tid, ar, br);
        __syncthreads();
        buf ^= 1;
    }
    proj_tile_mma(As[buf], Bs[buf], lane, wm0, wn0, acc);

    const int g = lane >> 2, lq = lane & 3;
    #pragma unroll
    for (int mt = 0; mt < 4; mt++) {
        int r = row0 + wm0 + mt * 16 + g;
        #pragma unroll
        for (int nt = 0; nt < 4; nt++) {
            int ccol = col0 + wn0 + nt * 8 + 2 * lq;
            float2 bv = *(const float2*)&bias[ccol];
            float2 o0 = { acc[mt][nt][0] + bv.x, acc[mt][nt][1] + bv.y };
            float2 o1 = { acc[mt][nt][2] + bv.x, acc[mt][nt][3] + bv.y };
            *(float2*)&Y[(size_t)r * DM + ccol]       = o0;
            *(float2*)&Y[(size_t)(r + 8) * DM + ccol] = o1;
        }
    }
}

// ===========================================================================
// Fused attention: scores + softmax + PV in one kernel.
// grid = (SEQ/128 = 16, B*H = 24), 256 threads.
// Two passes over key blocks of 64:
//   pass 0: S = Q K^T, p = mask*exp(S*scale), accumulate row sums l.
//   pass 1: recompute S, write probs = p/l (fp32), stage p/l as tf32 in smem,
//           O += P V (tensor). O comes out normalized; write to g_attn.
// No max subtraction: |s*scale| <= ~16 so exp never overflows; identical math.
// Dynamic smem: Qs[64][136] | KPs[64][136] (K tile then P^T tile) |
//               Vs[64][72] | maskf[2048] | row_l[128]   = 96768 B.
// ===========================================================================
#define SM_QS   0
#define SM_KPS  34816
#define SM_VS   (2 * 34816)
#define SM_MASK (2 * 34816 + 18432)
#define SM_ROWL (2 * 34816 + 18432 + 8192)
#define SM_FUSED_BYTES (SM_ROWL + 512)

__global__ __launch_bounds__(256, 2) void fused_attn(
    const int* __restrict__ mask, float* __restrict__ probs)
{
    extern __shared__ char smdyn[];
    uint32_t (*Qs)[136]  = (uint32_t(*)[136])(smdyn + SM_QS);
    uint32_t (*KPs)[136] = (uint32_t(*)[136])(smdyn + SM_KPS);
    uint32_t (*Vs)[72]   = (uint32_t(*)[72])(smdyn + SM_VS);
    float* maskf = (float*)(smdyn + SM_MASK);
    float* row_l = (float*)(smdyn + SM_ROWL);

    const int tid = threadIdx.x, lane = tid & 31, warp = tid >> 5;
    const int g = lane >> 2, lq = lane & 3;
    const int wm0 = (warp & 1) * 64, wn0 = (warp >> 1) * 16;   // S/O: 2x4 warps
    const int z = blockIdx.y, b = z / NH, h = z % NH;
    const int q0 = blockIdx.x * 128;

    const float* Qg = g_q + (size_t)b * SEQ * DM + h * DHD;
    const float* Kg = g_k + (size_t)b * SEQ * DM + h * DHD;
    const float* Vg = g_v + (size_t)b * SEQ * DM + h * DHD;
    float* P = probs + (size_t)z * SEQ * SEQ;

    // mask -> float 0/1 ; row_l init
    for (int i = tid; i < SEQ; i += 256)
        maskf[i] = (mask[b * SEQ + i] != 0) ? 1.f : 0.f;
    if (tid < 128) row_l[tid] = 0.f;

    // Q tile 128 x 64 -> Qs[kd][q] (tf32)
    #pragma unroll
    for (int t = 0; t < 8; t++) {
        int i = tid + t * 256;
        int r = i >> 4, c = (i & 15) * 4;
        float4 v = *(const float4*)(Qg + (size_t)(q0 + r) * DM + c);
        Qs[c + 0][r] = f2tf32(v.x);
        Qs[c + 1][r] = f2tf32(v.y);
        Qs[c + 2][r] = f2tf32(v.z);
        Qs[c + 3][r] = f2tf32(v.w);
    }
    __syncthreads();

    float oacc[4][2][4] = {};
    float rs[4][2] = {};

    for (int pass = 0; pass < 2; pass++) {
        for (int kb0 = 0; kb0 < SEQ; kb0 += KB) {
            __syncthreads();   // previous block's reads of KPs/Vs complete
            // K tile 64 keys x 64 kd -> KPs[kd][key] (tf32)
            #pragma unroll
            for (int t = 0; t < 4; t++) {
                int i = tid + t * 256;
                int n = i >> 4, c = (i & 15) * 4;
                float4 v = *(const float4*)(Kg + (size_t)(kb0 + n) * DM + c);
                KPs[c + 0][n] = f2tf32(v.x);
                KPs[c + 1][n] = f2tf32(v.y);
                KPs[c + 2][n] = f2tf32(v.z);
                KPs[c + 3][n] = f2tf32(v.w);
            }
            if (pass) {
                // V tile 64 keys x 64 d -> Vs[key][d] (tf32)
                #pragma unroll
                for (int t = 0; t < 4; t++) {
                    int i = tid + t * 256;
                    int n = i >> 4, c = (i & 15) * 4;
                    float4 v = *(const float4*)(Vg + (size_t)(kb0 + n) * DM + c);
                    Vs[n][c + 0] = f2tf32(v.x);
                    Vs[n][c + 1] = f2tf32(v.y);
                    Vs[n][c + 2] = f2tf32(v.z);
                    Vs[n][c + 3] = f2tf32(v.w);
                }
            }
            __syncthreads();

            // S = Q K^T  (128 x 64 tile)
            float sf[4][2][4] = {};
            #pragma unroll
            for (int ks = 0; ks < 64; ks += 8) {
                const int kb = ks + lq;
                uint32_t af[4][4], bf[2][2];
                #pragma unroll
                for (int mt = 0; mt < 4; mt++) {
                    int m = wm0 + mt * 16 + g;
                    af[mt][0] = Qs[kb][m];
                    af[mt][1] = Qs[kb][m + 8];
                    af[mt][2] = Qs[kb + 4][m];
                    af[mt][3] = Qs[kb + 4][m + 8];
                }
                #pragma unroll
                for (int nt = 0; nt < 2; nt++) {
                    int n = wn0 + nt * 8 + g;
                    bf[nt][0] = KPs[kb][n];
                    bf[nt][1] = KPs[kb + 4][n];
                }
                #pragma unroll
                for (int mt = 0; mt < 4; mt++)
                    #pragma unroll
                    for (int nt = 0; nt < 2; nt++)
                        mma8(sf[mt][nt], af[mt], bf[nt]);
            }

            if (pass) __syncthreads();   // all K reads done before P overwrite

            // mask + exp (+ rowsum | + normalized probs write + P^T stage)
            #pragma unroll
            for (int mt = 0; mt < 4; mt++) {
                int r0 = wm0 + mt * 16 + g;
                #pragma unroll
                for (int nt = 0; nt < 2; nt++) {
                    int cl  = wn0 + nt * 8 + 2 * lq;   // local col 0..63
                    int col = kb0 + cl;
                    float m0 = maskf[col], m1 = maskf[col + 1];
                    float p0 = m0 * __expf(sf[mt][nt][0] * ATT_SCALE);
                    float p1 = m1 * __expf(sf[mt][nt][1] * ATT_SCALE);
                    float p2 = m0 * __expf(sf[mt][nt][2] * ATT_SCALE);
                    float p3 = m1 * __expf(sf[mt][nt][3] * ATT_SCALE);
                    if (pass == 0) {
                        rs[mt][0] += p0 + p1;
                        rs[mt][1] += p2 + p3;
                    } else {
                        float i0 = row_l[r0], i1 = row_l[r0 + 8];
                        p0 *= i0; p1 *= i0; p2 *= i1; p3 *= i1;
                        float2 w0 = { p0, p1 }, w1 = { p2, p3 };
                        *(float2*)&P[(size_t)(q0 + r0) * SEQ + col]     = w0;
                        *(float2*)&P[(size_t)(q0 + r0 + 8) * SEQ + col] = w1;
                        KPs[cl][r0]         = f2tf32(p0);
                        KPs[cl + 1][r0]     = f2tf32(p1);
                        KPs[cl][r0 + 8]     = f2tf32(p2);
                        KPs[cl + 1][r0 + 8] = f2tf32(p3);
                    }
                }
            }

            if (pass) {
                __syncthreads();   // P^T staged
                // O += P V   (reduction over 64 keys)
                #pragma unroll
                for (int ks = 0; ks < 64; ks += 8) {
                    const int kb = ks + lq;
                    uint32_t af[4][4], bf[2][2];
                    #pragma unroll
                    for (int mt = 0; mt < 4; mt++) {
                        int m = wm0 + mt * 16 + g;
                        af[mt][0] = KPs[kb][m];
                        af[mt][1] = KPs[kb][m + 8];
                        af[mt][2] = KPs[kb + 4][m];
                        af[mt][3] = KPs[kb + 4][m + 8];
                    }
                    #pragma unroll
                    for (int nt = 0; nt < 2; nt++) {
                        int n = wn0 + nt * 8 + g;
                        bf[nt][0] = Vs[kb][n];
                        bf[nt][1] = Vs[kb + 4][n];
                    }
                    #pragma unroll
                    for (int mt = 0; mt < 4; mt++)
                        #pragma unroll
                        for (int nt = 0; nt < 2; nt++)
                            mma8(oacc[mt][nt], af[mt], bf[nt]);
                }
            }
        }

        if (pass == 0) {
            // reduce per-thread row sums into row_l, then invert
            #pragma unroll
            for (int mt = 0; mt < 4; mt++)
                #pragma unroll
                for (int hh = 0; hh < 2; hh++) {
                    float v = rs[mt][hh];
                    v += __shfl_xor_sync(0xffffffffu, v, 1);
                    v += __shfl_xor_sync(0xffffffffu, v, 2);
                    if (lq == 0)
                        atomicAdd(&row_l[wm0 + mt * 16 + hh * 8 + g], v);
                }
            __syncthreads();
            if (tid < 128) row_l[tid] = 1.f / row_l[tid];
            __syncthreads();
        }
    }

    // O (already normalized) -> g_attn
    float* Og = g_attn + (size_t)b * SEQ * DM + h * DHD + (size_t)q0 * DM;
    #pragma unroll
    for (int mt = 0; mt < 4; mt++) {
        int r = wm0 + mt * 16 + g;
        #pragma unroll
        for (int nt = 0; nt < 2; nt++) {
            int c = wn0 + nt * 8 + 2 * lq;
            float2 o0 = { oacc[mt][nt][0], oacc[mt][nt][1] };
            float2 o1 = { oacc[mt][nt][2], oacc[mt][nt][3] };
            *(float2*)&Og[(size_t)r * DM + c]       = o0;
            *(float2*)&Og[(size_t)(r + 8) * DM + c] = o1;
        }
    }
}

// ---------------------------------------------------------------------------
extern "C" void kernel_launch(void* const* d_in, const int* in_sizes, int n_in,
                              void* d_out, int out_size)
{
    const float* query = (const float*)d_in[0];
    const float* key   = (const float*)d_in[1];
    const float* value = (const float*)d_in[2];
    const int*   mask  = (const int*)d_in[3];
    const float* wq = (const float*)d_in[4];
    const float* bq = (const float*)d_in[5];
    const float* wk = (const float*)d_in[6];
    const float* bk = (const float*)d_in[7];
    const float* wv = (const float*)d_in[8];
    const float* bv = (const float*)d_in[9];
    const float* wo = (const float*)d_in[10];
    const float* bo = (const float*)d_in[11];

    float* out   = (float*)d_out;                       // [B, S, D]
    float* probs = out + (size_t)BATCH * SEQ * DM;      // [B, H, S, S]

    float *qp, *kp, *vp, *ap;
    cudaGetSymbolAddress((void**)&qp, g_q);
    cudaGetSymbolAddress((void**)&kp, g_k);
    cudaGetSymbolAddress((void**)&vp, g_v);
    cudaGetSymbolAddress((void**)&ap, g_attn);

    cudaFuncSetAttribute(fused_attn,
                         cudaFuncAttributeMaxDynamicSharedMemorySize,
                         SM_FUSED_BYTES);

    dim3 proj_grid(DM / 128, (BATCH * SEQ) / 128);      // (6, 32)
    proj_kernel<<<proj_grid, 256>>>(query, wq, bq, qp);
    proj_kernel<<<proj_grid, 256>>>(key,   wk, bk, kp);
    proj_kernel<<<proj_grid, 256>>>(value, wv, bv, vp);

    dim3 f_grid(SEQ / 128, BATCH * NH);                 // (16, 24)
    fused_attn<<<f_grid, 256, SM_FUSED_BYTES>>>(mask, probs);

    proj_kernel<<<proj_grid, 256>>>(ap, wo, bo, out);
}